// round 8
// baseline (speedup 1.0000x reference)
#include <cuda_runtime.h>
#include <cuda_bf16.h>
#include <cuda_fp16.h>
#include <cstdint>

#define FM        64
#define MAXV      100000
#define MAXC      50000
#define MAXNNZ    2000000
#define OUTB      16

typedef unsigned long long u64;
typedef unsigned int u32;

// ===================== scratch globals ======================================
__device__ float g_vars[MAXV * FM];
__device__ float g_cons[MAXC * FM];
__device__ float g_v2c [MAXC * FM];
__device__ float g_c2v [MAXV * FM];

// half2-packed mirrors for the gather path (32 u32 per row)
__device__ u32   g_varsH[MAXV * 32];
__device__ u32   g_consH[MAXC * 32];

__device__ int   g_cntC[MAXC];
__device__ int   g_cntV[MAXV];
__device__ int   g_offC[MAXC + 1];
__device__ int   g_offV[MAXV + 1];
__device__ int   g_curC[MAXC];
__device__ int   g_curV[MAXV];

// packed edge entries: low 32 = index, high 32 = fp32 bits of |val|
__device__ u64   g_cscE[MAXNNZ];
__device__ u64   g_csrE[MAXNNZ];

// packed per-lane weight fragments (uint4 = {b0_hi, b1_hi, b0_lo, b1_lo})
__device__ u32 g_w1p_cu[16384];
__device__ u32 g_w2p_cu[8192];
__device__ u32 g_w1p_vu[16384];
__device__ u32 g_w2p_vu[8192];
__device__ u32 g_w1p_out[8192];
__device__ u32 g_w2p_out[2048];

// ===================== helpers ==============================================
__device__ __forceinline__ void bfsplit2(float f0, float f1, u32& hi, u32& lo) {
    __nv_bfloat162 h, l;
    h.x = __float2bfloat16(f0);
    h.y = __float2bfloat16(f1);
    l.x = __float2bfloat16(f0 - __bfloat162float(h.x));
    l.y = __float2bfloat16(f1 - __bfloat162float(h.y));
    hi = *(u32*)&h;
    lo = *(u32*)&l;
}

__device__ __forceinline__ u32 pkhalf2(float f0, float f1) {
    __half2 h = __floats2half2_rn(f0, f1);
    return *(u32*)&h;
}

__device__ __forceinline__ void mma_bf16(float* d, u32 a0, u32 a1, u32 a2, u32 a3,
                                         u32 b0, u32 b1) {
    asm volatile(
        "mma.sync.aligned.m16n8k16.row.col.f32.bf16.bf16.f32 "
        "{%0,%1,%2,%3}, {%4,%5,%6,%7}, {%8,%9}, {%0,%1,%2,%3};"
        : "+f"(d[0]), "+f"(d[1]), "+f"(d[2]), "+f"(d[3])
        : "r"(a0), "r"(a1), "r"(a2), "r"(a3), "r"(b0), "r"(b1));
}

// ===================== CSR/CSC build ========================================
__global__ void zero_counts_kernel(int nC, int nV) {
    int i = blockIdx.x * blockDim.x + threadIdx.x;
    if (i < nC) g_cntC[i] = 0;
    if (i < nV) g_cntV[i] = 0;
}

__global__ void hist_kernel(const int* __restrict__ row, const int* __restrict__ col, int nnz) {
    int base = blockIdx.x * blockDim.x * 8 + threadIdx.x;
#pragma unroll
    for (int j = 0; j < 8; j++) {
        int e = base + j * blockDim.x;
        if (e < nnz) {
            atomicAdd(&g_cntC[col[e]], 1);
            atomicAdd(&g_cntV[row[e]], 1);
        }
    }
}

__global__ void scan_kernel(int nC, int nV) {
    const int* cnt; int* off; int* cur; int n;
    if (blockIdx.x == 0) { cnt = g_cntC; off = g_offC; cur = g_curC; n = nC; }
    else                 { cnt = g_cntV; off = g_offV; cur = g_curV; n = nV; }

    __shared__ int part[1024];
    int t = threadIdx.x;
    int chunk = (n + 1023) / 1024;
    int beg = t * chunk;
    int end = min(n, beg + chunk);

    int s = 0;
    for (int i = beg; i < end; i++) s += cnt[i];
    part[t] = s;
    __syncthreads();
    for (int d = 1; d < 1024; d <<= 1) {
        int v = (t >= d) ? part[t - d] : 0;
        __syncthreads();
        part[t] += v;
        __syncthreads();
    }
    int run = (t == 0) ? 0 : part[t - 1];
    for (int i = beg; i < end; i++) {
        off[i] = run; cur[i] = run;
        run += cnt[i];
    }
    if (t == 1023) off[n] = part[1023];
}

__global__ void fill_kernel(const int* __restrict__ row, const int* __restrict__ col,
                            const float* __restrict__ av, int nnz) {
    int base = blockIdx.x * blockDim.x * 4 + threadIdx.x;
    int e[4], r[4], c[4];
    u32 vb[4];
    bool ok[4];
#pragma unroll
    for (int j = 0; j < 4; j++) {
        e[j] = base + j * blockDim.x;
        ok[j] = e[j] < nnz;
        if (ok[j]) {
            r[j] = row[e[j]];
            c[j] = col[e[j]];
            vb[j] = __float_as_uint(fabsf(av[e[j]]));
        }
    }
    int p[4], q[4];
#pragma unroll
    for (int j = 0; j < 4; j++) {
        if (ok[j]) {
            p[j] = atomicAdd(&g_curC[c[j]], 1);
            q[j] = atomicAdd(&g_curV[r[j]], 1);
        }
    }
#pragma unroll
    for (int j = 0; j < 4; j++) {
        if (ok[j]) {
            g_cscE[p[j]] = ((u64)vb[j] << 32) | (u32)r[j];
            g_csrE[q[j]] = ((u64)vb[j] << 32) | (u32)c[j];
        }
    }
}

__global__ void init_vars_kernel(int nf, int nh) {
    int i = blockIdx.x * blockDim.x + threadIdx.x;
    if (i < nf) g_vars[i] = 1.0f;
    if (i < nh) g_varsH[i] = 0x3C003C00u;   // half2(1.0, 1.0)
}

// ===================== weight fragment packing ==============================
__global__ void conv_w_kernel(const float* __restrict__ W1, const float* __restrict__ W2,
                              u32* __restrict__ w1p, u32* __restrict__ w2p) {
    int idx = blockIdx.x * blockDim.x + threadIdx.x;   // 16384 threads
    {
        int pos  = idx & 3;
        int lane = (idx >> 2) & 31;
        int j    = (idx >> 7) & 15;
        int t    = idx >> 11;
        int k = t * 16 + 2 * (lane & 3) + ((pos & 1) ? 8 : 0);
        int n = j * 8 + (lane >> 2);
        float f0 = W1[k * 128 + n];
        float f1 = W1[(k + 1) * 128 + n];
        u32 hi, lo;
        bfsplit2(f0, f1, hi, lo);
        w1p[idx] = (pos >= 2) ? lo : hi;
    }
    if (idx < 8192) {
        int pos  = idx & 3;
        int lane = (idx >> 2) & 31;
        int j    = (idx >> 7) & 7;
        int t    = idx >> 10;
        int k = t * 16 + 2 * (lane & 3) + ((pos & 1) ? 8 : 0);
        int n = j * 8 + (lane >> 2);
        float f0 = W2[k * 64 + n];
        float f1 = W2[(k + 1) * 64 + n];
        u32 hi, lo;
        bfsplit2(f0, f1, hi, lo);
        w2p[idx] = (pos >= 2) ? lo : hi;
    }
}

__global__ void conv_w_out_kernel(const float* __restrict__ W1, const float* __restrict__ W2,
                                  u32* __restrict__ w1p, u32* __restrict__ w2p) {
    int idx = blockIdx.x * blockDim.x + threadIdx.x;   // 8192 threads
    {
        int pos  = idx & 3;
        int lane = (idx >> 2) & 31;
        int j    = (idx >> 7) & 15;
        int t    = idx >> 11;            // 0..3
        int k = t * 16 + 2 * (lane & 3) + ((pos & 1) ? 8 : 0);
        int n = j * 8 + (lane >> 2);
        float f0 = W1[k * 128 + n];
        float f1 = W1[(k + 1) * 128 + n];
        u32 hi, lo;
        bfsplit2(f0, f1, hi, lo);
        w1p[idx] = (pos >= 2) ? lo : hi;
    }
    if (idx < 2048) {
        int pos  = idx & 3;
        int lane = (idx >> 2) & 31;
        int j    = (idx >> 7) & 1;
        int t    = idx >> 8;             // 0..7
        int k = t * 16 + 2 * (lane & 3) + ((pos & 1) ? 8 : 0);
        int n = j * 8 + (lane >> 2);
        float f0 = W2[k * 16 + n];
        float f1 = W2[(k + 1) * 16 + n];
        u32 hi, lo;
        bfsplit2(f0, f1, hi, lo);
        w2p[idx] = (pos >= 2) ? lo : hi;
    }
}

// ===================== segment gather-reduce (half2 features) ==============
__global__ void seg_gather_kernel(const int* __restrict__ offs,
                                  const u64* __restrict__ edges,
                                  const u32* __restrict__ srcH,
                                  float* __restrict__ dstF, int nseg) {
    int warp = threadIdx.x >> 5;
    int lane = threadIdx.x & 31;
    int seg  = blockIdx.x * (blockDim.x >> 5) + warp;
    if (seg >= nseg) return;

    int s = offs[seg], e = offs[seg + 1];
    float ax = 0.f, ay = 0.f;
    int p = s;
    for (; p + 4 <= e; p += 4) {
        u64 e0 = __ldg(&edges[p + 0]);
        u64 e1 = __ldg(&edges[p + 1]);
        u64 e2 = __ldg(&edges[p + 2]);
        u64 e3 = __ldg(&edges[p + 3]);
        u32 h0 = __ldg(&srcH[(size_t)(u32)e0 * 32 + lane]);
        u32 h1 = __ldg(&srcH[(size_t)(u32)e1 * 32 + lane]);
        u32 h2 = __ldg(&srcH[(size_t)(u32)e2 * 32 + lane]);
        u32 h3 = __ldg(&srcH[(size_t)(u32)e3 * 32 + lane]);
        float2 f0 = __half22float2(*(const __half2*)&h0);
        float2 f1 = __half22float2(*(const __half2*)&h1);
        float2 f2 = __half22float2(*(const __half2*)&h2);
        float2 f3 = __half22float2(*(const __half2*)&h3);
        float v0 = __uint_as_float((u32)(e0 >> 32));
        float v1 = __uint_as_float((u32)(e1 >> 32));
        float v2 = __uint_as_float((u32)(e2 >> 32));
        float v3 = __uint_as_float((u32)(e3 >> 32));
        ax += v0 * f0.x; ay += v0 * f0.y;
        ax += v1 * f1.x; ay += v1 * f1.y;
        ax += v2 * f2.x; ay += v2 * f2.y;
        ax += v3 * f3.x; ay += v3 * f3.y;
    }
    for (; p < e; p++) {
        u64 e0 = __ldg(&edges[p]);
        u32 h0 = __ldg(&srcH[(size_t)(u32)e0 * 32 + lane]);
        float2 f0 = __half22float2(*(const __half2*)&h0);
        float v0 = __uint_as_float((u32)(e0 >> 32));
        ax += v0 * f0.x; ay += v0 * f0.y;
    }
    *(float2*)&dstF[(size_t)seg * FM + 2 * lane] = make_float2(ax, ay);
}

// ===================== MMA MLP: concat(inA,inB)->128(relu)->64 ==============
// Also writes a half2-packed mirror of the output (for the next gather).
__global__ void __launch_bounds__(256) mlp_mma_kernel(
        const float* __restrict__ inA, const float* __restrict__ inB,
        float* __restrict__ outp, u32* __restrict__ outH,
        const uint4* __restrict__ w1p, const float* __restrict__ b1,
        const uint4* __restrict__ w2p, const float* __restrict__ b2,
        int rows) {
    int tid = threadIdx.x;
    int wid = tid >> 5;
    int lane = tid & 31;
    int m = lane & 3;
    int g = lane >> 2;

    int rbase = blockIdx.x * 128 + wid * 16;
    if (rbase >= rows) return;
    int r0 = rbase + g, r1 = rbase + g + 8;
    int rr0 = min(r0, rows - 1), rr1 = min(r1, rows - 1);

    float d1[16][4];
#pragma unroll
    for (int j = 0; j < 16; j++)
#pragma unroll
        for (int q = 0; q < 4; q++) d1[j][q] = 0.f;

#pragma unroll
    for (int t = 0; t < 8; t++) {
        const float* src = (t < 4) ? inA : inB;
        int kc = (t & 3) * 16 + 2 * m;
        float2 x0 = *(const float2*)&src[(size_t)rr0 * 64 + kc];
        float2 x1 = *(const float2*)&src[(size_t)rr1 * 64 + kc];
        float2 x2 = *(const float2*)&src[(size_t)rr0 * 64 + kc + 8];
        float2 x3 = *(const float2*)&src[(size_t)rr1 * 64 + kc + 8];
        u32 ah0, al0, ah1, al1, ah2, al2, ah3, al3;
        bfsplit2(x0.x, x0.y, ah0, al0);
        bfsplit2(x1.x, x1.y, ah1, al1);
        bfsplit2(x2.x, x2.y, ah2, al2);
        bfsplit2(x3.x, x3.y, ah3, al3);

        const uint4* wp = w1p + (size_t)(t * 16) * 32 + lane;
#pragma unroll
        for (int j = 0; j < 16; j++) {
            uint4 w = __ldg(&wp[j * 32]);
            mma_bf16(d1[j], ah0, ah1, ah2, ah3, w.x, w.y);
            mma_bf16(d1[j], ah0, ah1, ah2, ah3, w.z, w.w);
            mma_bf16(d1[j], al0, al1, al2, al3, w.x, w.y);
        }
    }

    float d2[8][4];
#pragma unroll
    for (int j = 0; j < 8; j++)
#pragma unroll
        for (int q = 0; q < 4; q++) d2[j][q] = 0.f;

#pragma unroll
    for (int t = 0; t < 8; t++) {
        float2 ba = *(const float2*)&b1[16 * t + 2 * m];
        float2 bb = *(const float2*)&b1[16 * t + 8 + 2 * m];
        float f0 = fmaxf(d1[2 * t][0] + ba.x, 0.f);
        float f1 = fmaxf(d1[2 * t][1] + ba.y, 0.f);
        float f2 = fmaxf(d1[2 * t][2] + ba.x, 0.f);
        float f3 = fmaxf(d1[2 * t][3] + ba.y, 0.f);
        float f4 = fmaxf(d1[2 * t + 1][0] + bb.x, 0.f);
        float f5 = fmaxf(d1[2 * t + 1][1] + bb.y, 0.f);
        float f6 = fmaxf(d1[2 * t + 1][2] + bb.x, 0.f);
        float f7 = fmaxf(d1[2 * t + 1][3] + bb.y, 0.f);
        u32 ah0, al0, ah1, al1, ah2, al2, ah3, al3;
        bfsplit2(f0, f1, ah0, al0);
        bfsplit2(f2, f3, ah1, al1);
        bfsplit2(f4, f5, ah2, al2);
        bfsplit2(f6, f7, ah3, al3);

        const uint4* wp = w2p + (size_t)(t * 8) * 32 + lane;
#pragma unroll
        for (int j = 0; j < 8; j++) {
            uint4 w = __ldg(&wp[j * 32]);
            mma_bf16(d2[j], ah0, ah1, ah2, ah3, w.x, w.y);
            mma_bf16(d2[j], ah0, ah1, ah2, ah3, w.z, w.w);
            mma_bf16(d2[j], al0, al1, al2, al3, w.x, w.y);
        }
    }

#pragma unroll
    for (int j = 0; j < 8; j++) {
        float2 b = *(const float2*)&b2[8 * j + 2 * m];
        float o0 = d2[j][0] + b.x, o1 = d2[j][1] + b.y;
        float o2 = d2[j][2] + b.x, o3 = d2[j][3] + b.y;
        if (r0 < rows) {
            *(float2*)&outp[(size_t)r0 * 64 + 8 * j + 2 * m] = make_float2(o0, o1);
            outH[(size_t)r0 * 32 + 4 * j + m] = pkhalf2(o0, o1);
        }
        if (r1 < rows) {
            *(float2*)&outp[(size_t)r1 * 64 + 8 * j + 2 * m] = make_float2(o2, o3);
            outH[(size_t)r1 * 32 + 4 * j + m] = pkhalf2(o2, o3);
        }
    }
}

// ===================== MMA output MLP: vars[64]->128(relu)->16 + sigmoid ====
__global__ void __launch_bounds__(256) out_mma_kernel(
        const uint4* __restrict__ w1p, const float* __restrict__ b1,
        const uint4* __restrict__ w2p, const float* __restrict__ b2,
        float* __restrict__ outp, int rows) {
    int tid = threadIdx.x;
    int wid = tid >> 5;
    int lane = tid & 31;
    int m = lane & 3;
    int g = lane >> 2;

    int rbase = blockIdx.x * 128 + wid * 16;
    if (rbase >= rows) return;
    int r0 = rbase + g, r1 = rbase + g + 8;
    int rr0 = min(r0, rows - 1), rr1 = min(r1, rows - 1);

    float d1[16][4];
#pragma unroll
    for (int j = 0; j < 16; j++)
#pragma unroll
        for (int q = 0; q < 4; q++) d1[j][q] = 0.f;

#pragma unroll
    for (int t = 0; t < 4; t++) {
        int kc = t * 16 + 2 * m;
        float2 x0 = *(const float2*)&g_vars[(size_t)rr0 * 64 + kc];
        float2 x1 = *(const float2*)&g_vars[(size_t)rr1 * 64 + kc];
        float2 x2 = *(const float2*)&g_vars[(size_t)rr0 * 64 + kc + 8];
        float2 x3 = *(const float2*)&g_vars[(size_t)rr1 * 64 + kc + 8];
        u32 ah0, al0, ah1, al1, ah2, al2, ah3, al3;
        bfsplit2(x0.x, x0.y, ah0, al0);
        bfsplit2(x1.x, x1.y, ah1, al1);
        bfsplit2(x2.x, x2.y, ah2, al2);
        bfsplit2(x3.x, x3.y, ah3, al3);

        const uint4* wp = w1p + (size_t)(t * 16) * 32 + lane;
#pragma unroll
        for (int j = 0; j < 16; j++) {
            uint4 w = __ldg(&wp[j * 32]);
            mma_bf16(d1[j], ah0, ah1, ah2, ah3, w.x, w.y);
            mma_bf16(d1[j], ah0, ah1, ah2, ah3, w.z, w.w);
            mma_bf16(d1[j], al0, al1, al2, al3, w.x, w.y);
        }
    }

    float d2[2][4];
#pragma unroll
    for (int j = 0; j < 2; j++)
#pragma unroll
        for (int q = 0; q < 4; q++) d2[j][q] = 0.f;

#pragma unroll
    for (int t = 0; t < 8; t++) {
        float2 ba = *(const float2*)&b1[16 * t + 2 * m];
        float2 bb = *(const float2*)&b1[16 * t + 8 + 2 * m];
        float f0 = fmaxf(d1[2 * t][0] + ba.x, 0.f);
        float f1 = fmaxf(d1[2 * t][1] + ba.y, 0.f);
        float f2 = fmaxf(d1[2 * t][2] + ba.x, 0.f);
        float f3 = fmaxf(d1[2 * t][3] + ba.y, 0.f);
        float f4 = fmaxf(d1[2 * t + 1][0] + bb.x, 0.f);
        float f5 = fmaxf(d1[2 * t + 1][1] + bb.y, 0.f);
        float f6 = fmaxf(d1[2 * t + 1][2] + bb.x, 0.f);
        float f7 = fmaxf(d1[2 * t + 1][3] + bb.y, 0.f);
        u32 ah0, al0, ah1, al1, ah2, al2, ah3, al3;
        bfsplit2(f0, f1, ah0, al0);
        bfsplit2(f2, f3, ah1, al1);
        bfsplit2(f4, f5, ah2, al2);
        bfsplit2(f6, f7, ah3, al3);

        const uint4* wp = w2p + (size_t)(t * 2) * 32 + lane;
#pragma unroll
        for (int j = 0; j < 2; j++) {
            uint4 w = __ldg(&wp[j * 32]);
            mma_bf16(d2[j], ah0, ah1, ah2, ah3, w.x, w.y);
            mma_bf16(d2[j], ah0, ah1, ah2, ah3, w.z, w.w);
            mma_bf16(d2[j], al0, al1, al2, al3, w.x, w.y);
        }
    }

#pragma unroll
    for (int j = 0; j < 2; j++) {
        float2 b = *(const float2*)&b2[8 * j + 2 * m];
        if (r0 < rows) {
            float z0 = d2[j][0] + b.x;
            float z1 = d2[j][1] + b.y;
            *(float2*)&outp[(size_t)r0 * OUTB + 8 * j + 2 * m] =
                make_float2(1.f / (1.f + __expf(-z0)), 1.f / (1.f + __expf(-z1)));
        }
        if (r1 < rows) {
            float z2 = d2[j][2] + b.x;
            float z3 = d2[j][3] + b.y;
            *(float2*)&outp[(size_t)r1 * OUTB + 8 * j + 2 * m] =
                make_float2(1.f / (1.f + __expf(-z2)), 1.f / (1.f + __expf(-z3)));
        }
    }
}

// ===================== scalar prep kernel ===================================
__device__ __forceinline__ void mlp_layer2_64(const float* sbuf,
                                              const float* __restrict__ W2,
                                              const float* __restrict__ b2,
                                              float* __restrict__ outp,
                                              int row0, int rows, int lane) {
    float2 acc[4];
#pragma unroll
    for (int r = 0; r < 4; r++) acc[r] = make_float2(0.f, 0.f);

    for (int k = 0; k < 128; k += 4) {
        float4 hv[4];
#pragma unroll
        for (int r = 0; r < 4; r++) hv[r] = *(const float4*)&sbuf[r * 128 + k];
#pragma unroll
        for (int kk = 0; kk < 4; kk++) {
            float2 w = *(const float2*)&W2[(k + kk) * 64 + 2 * lane];
#pragma unroll
            for (int r = 0; r < 4; r++) {
                float hk = ((const float*)&hv[r])[kk];
                acc[r].x += hk * w.x;
                acc[r].y += hk * w.y;
            }
        }
    }
    float2 bb = *(const float2*)&b2[2 * lane];
#pragma unroll
    for (int r = 0; r < 4; r++) {
        if (row0 + r < rows) {
            *(float2*)&outp[(size_t)(row0 + r) * 64 + 2 * lane] =
                make_float2(acc[r].x + bb.x, acc[r].y + bb.y);
        }
    }
}

__global__ void __launch_bounds__(256) prep_kernel(
                            const float* __restrict__ cond,
                            const float* __restrict__ w1, const float* __restrict__ b1,
                            const float* __restrict__ w2, const float* __restrict__ b2,
                            int rows) {
    __shared__ float sbuf[8][512];
    int warp = threadIdx.x >> 5;
    int lane = threadIdx.x & 31;
    int row0 = (blockIdx.x * 8 + warp) * 4;
    if (row0 >= rows) return;
    float* sbf = sbuf[warp];

    float4 w = *(const float4*)&w1[4 * lane];
    float4 b = *(const float4*)&b1[4 * lane];
#pragma unroll
    for (int r = 0; r < 4; r++) {
        int row = min(row0 + r, rows - 1);
        float c = cond[row];
        float4 h;
        h.x = fmaxf(c * w.x + b.x, 0.f);
        h.y = fmaxf(c * w.y + b.y, 0.f);
        h.z = fmaxf(c * w.z + b.z, 0.f);
        h.w = fmaxf(c * w.w + b.w, 0.f);
        *(float4*)&sbf[r * 128 + 4 * lane] = h;
    }
    __syncwarp();
    mlp_layer2_64(sbf, w2, b2, g_cons, row0, rows, lane);
}

// ===================== launch ===============================================
extern "C" void kernel_launch(void* const* d_in, const int* in_sizes, int n_in,
                              void* d_out, int out_size) {
    const int*   row  = (const int*)  d_in[0];
    const int*   col  = (const int*)  d_in[1];
    const float* adj  = (const float*)d_in[2];
    const float* cond = (const float*)d_in[3];

    int nnz = in_sizes[0];
    int C   = in_sizes[3];
    int V   = out_size / OUTB;
    if (nnz > MAXNNZ) nnz = MAXNNZ;
    if (C > MAXC) C = MAXC;
    if (V > MAXV) V = MAXV;

    int w = 4;
    if (n_in >= 22 && in_sizes[4] == 1 && in_sizes[5] == 1) w = 6;
    const float* pc_w1 = (const float*)d_in[w + 0];
    const float* pc_b1 = (const float*)d_in[w + 1];
    const float* pc_w2 = (const float*)d_in[w + 2];
    const float* pc_b2 = (const float*)d_in[w + 3];
    const float* cu_w1 = (const float*)d_in[w + 4];
    const float* cu_b1 = (const float*)d_in[w + 5];
    const float* cu_w2 = (const float*)d_in[w + 6];
    const float* cu_b2 = (const float*)d_in[w + 7];
    const float* vu_w1 = (const float*)d_in[w + 8];
    const float* vu_b1 = (const float*)d_in[w + 9];
    const float* vu_w2 = (const float*)d_in[w + 10];
    const float* vu_b2 = (const float*)d_in[w + 11];
    const float* o_w1  = (const float*)d_in[w + 12];
    const float* o_b1  = (const float*)d_in[w + 13];
    const float* o_w2  = (const float*)d_in[w + 14];
    const float* o_b2  = (const float*)d_in[w + 15];

    float *p_vars, *p_cons, *p_v2c, *p_c2v;
    u32   *p_varsH, *p_consH;
    int   *p_offC, *p_offV;
    u64   *p_cscE, *p_csrE;
    u32   *p_w1cu, *p_w2cu, *p_w1vu, *p_w2vu, *p_w1o, *p_w2o;
    cudaGetSymbolAddress((void**)&p_vars,  g_vars);
    cudaGetSymbolAddress((void**)&p_cons,  g_cons);
    cudaGetSymbolAddress((void**)&p_v2c,   g_v2c);
    cudaGetSymbolAddress((void**)&p_c2v,   g_c2v);
    cudaGetSymbolAddress((void**)&p_varsH, g_varsH);
    cudaGetSymbolAddress((void**)&p_consH, g_consH);
    cudaGetSymbolAddress((void**)&p_offC,  g_offC);
    cudaGetSymbolAddress((void**)&p_offV,  g_offV);
    cudaGetSymbolAddress((void**)&p_cscE,  g_cscE);
    cudaGetSymbolAddress((void**)&p_csrE,  g_csrE);
    cudaGetSymbolAddress((void**)&p_w1cu,  g_w1p_cu);
    cudaGetSymbolAddress((void**)&p_w2cu,  g_w2p_cu);
    cudaGetSymbolAddress((void**)&p_w1vu,  g_w1p_vu);
    cudaGetSymbolAddress((void**)&p_w2vu,  g_w2p_vu);
    cudaGetSymbolAddress((void**)&p_w1o,   g_w1p_out);
    cudaGetSymbolAddress((void**)&p_w2o,   g_w2p_out);

    int maxCV = (C > V) ? C : V;

    zero_counts_kernel<<<(maxCV + 255) / 256, 256>>>(C, V);
    hist_kernel<<<(nnz + 2047) / 2048, 256>>>(row, col, nnz);
    scan_kernel<<<2, 1024>>>(C, V);
    fill_kernel<<<(nnz + 1023) / 1024, 256>>>(row, col, adj, nnz);
    init_vars_kernel<<<(V * FM + 255) / 256, 256>>>(V * FM, V * 32);
    conv_w_kernel<<<64, 256>>>(cu_w1, cu_w2, p_w1cu, p_w2cu);
    conv_w_kernel<<<64, 256>>>(vu_w1, vu_w2, p_w1vu, p_w2vu);
    conv_w_out_kernel<<<32, 256>>>(o_w1, o_w2, p_w1o, p_w2o);
    prep_kernel<<<(C + 31) / 32, 256>>>(cond, pc_w1, pc_b1, pc_w2, pc_b2, C);

    int gC = (C + 127) / 128;
    int gV = (V + 127) / 128;
    for (int it = 0; it < 3; it++) {
        seg_gather_kernel<<<(C + 7) / 8, 256>>>(p_offC, p_cscE, p_varsH, p_v2c, C);
        mlp_mma_kernel<<<gC, 256>>>(p_cons, p_v2c, p_cons, p_consH,
                                    (const uint4*)p_w1cu, cu_b1, (const uint4*)p_w2cu, cu_b2, C);
        seg_gather_kernel<<<(V + 7) / 8, 256>>>(p_offV, p_csrE, p_consH, p_c2v, V);
        mlp_mma_kernel<<<gV, 256>>>(p_vars, p_c2v, p_vars, p_varsH,
                                    (const uint4*)p_w1vu, vu_b1, (const uint4*)p_w2vu, vu_b2, V);
    }

    out_mma_kernel<<<gV, 256>>>((const uint4*)p_w1o, o_b1, (const uint4*)p_w2o, o_b2,
                                (float*)d_out, V);
}

// round 9
// speedup vs baseline: 1.0212x; 1.0212x over previous
#include <cuda_runtime.h>
#include <cuda_bf16.h>
#include <cstdint>

#define FM        64
#define MAXV      100000
#define MAXC      50000
#define MAXNNZ    2000000
#define OUTB      16

typedef unsigned long long u64;
typedef unsigned int u32;

// ===================== scratch globals ======================================
__device__ float g_vars[MAXV * FM];
__device__ float g_cons[MAXC * FM];
__device__ float g_v2c [MAXC * FM];
__device__ float g_c2v [MAXV * FM];

__device__ int   g_cntC[MAXC];
__device__ int   g_cntV[MAXV];
__device__ int   g_offC[MAXC + 1];
__device__ int   g_offV[MAXV + 1];
__device__ int   g_curC[MAXC];
__device__ int   g_curV[MAXV];

// packed edge entries: low 32 = index, high 32 = fp32 bits of |val|
__device__ u64   g_cscE[MAXNNZ];
__device__ u64   g_csrE[MAXNNZ];

// packed per-lane weight fragments (uint4 = {b0_hi, b1_hi, b0_lo, b1_lo})
__device__ u32 g_w1p_cu[16384];
__device__ u32 g_w2p_cu[8192];
__device__ u32 g_w1p_vu[16384];
__device__ u32 g_w2p_vu[8192];
__device__ u32 g_w1p_out[8192];
__device__ u32 g_w2p_out[2048];

// ===================== helpers ==============================================
__device__ __forceinline__ void bfsplit2(float f0, float f1, u32& hi, u32& lo) {
    __nv_bfloat162 h, l;
    h.x = __float2bfloat16(f0);
    h.y = __float2bfloat16(f1);
    l.x = __float2bfloat16(f0 - __bfloat162float(h.x));
    l.y = __float2bfloat16(f1 - __bfloat162float(h.y));
    hi = *(u32*)&h;
    lo = *(u32*)&l;
}

__device__ __forceinline__ void mma_bf16(float* d, u32 a0, u32 a1, u32 a2, u32 a3,
                                         u32 b0, u32 b1) {
    asm volatile(
        "mma.sync.aligned.m16n8k16.row.col.f32.bf16.bf16.f32 "
        "{%0,%1,%2,%3}, {%4,%5,%6,%7}, {%8,%9}, {%0,%1,%2,%3};"
        : "+f"(d[0]), "+f"(d[1]), "+f"(d[2]), "+f"(d[3])
        : "r"(a0), "r"(a1), "r"(a2), "r"(a3), "r"(b0), "r"(b1));
}

// ===================== CSR/CSC build ========================================
__global__ void zero_counts_kernel(int nC, int nV) {
    int i = blockIdx.x * blockDim.x + threadIdx.x;
    if (i < nC) g_cntC[i] = 0;
    if (i < nV) g_cntV[i] = 0;
}

__global__ void hist_kernel(const int* __restrict__ row, const int* __restrict__ col, int nnz) {
    int base = blockIdx.x * blockDim.x * 8 + threadIdx.x;
#pragma unroll
    for (int j = 0; j < 8; j++) {
        int e = base + j * blockDim.x;
        if (e < nnz) {
            atomicAdd(&g_cntC[col[e]], 1);
            atomicAdd(&g_cntV[row[e]], 1);
        }
    }
}

__global__ void scan_kernel(int nC, int nV) {
    const int* cnt; int* off; int* cur; int n;
    if (blockIdx.x == 0) { cnt = g_cntC; off = g_offC; cur = g_curC; n = nC; }
    else                 { cnt = g_cntV; off = g_offV; cur = g_curV; n = nV; }

    __shared__ int part[1024];
    int t = threadIdx.x;
    int chunk = (n + 1023) / 1024;
    int beg = t * chunk;
    int end = min(n, beg + chunk);

    int s = 0;
    for (int i = beg; i < end; i++) s += cnt[i];
    part[t] = s;
    __syncthreads();
    for (int d = 1; d < 1024; d <<= 1) {
        int v = (t >= d) ? part[t - d] : 0;
        __syncthreads();
        part[t] += v;
        __syncthreads();
    }
    int run = (t == 0) ? 0 : part[t - 1];
    for (int i = beg; i < end; i++) {
        off[i] = run; cur[i] = run;
        run += cnt[i];
    }
    if (t == 1023) off[n] = part[1023];
}

__global__ void fill_kernel(const int* __restrict__ row, const int* __restrict__ col,
                            const float* __restrict__ av, int nnz) {
    int base = blockIdx.x * blockDim.x * 4 + threadIdx.x;
    int e[4], r[4], c[4];
    u32 vb[4];
    bool ok[4];
#pragma unroll
    for (int j = 0; j < 4; j++) {
        e[j] = base + j * blockDim.x;
        ok[j] = e[j] < nnz;
        if (ok[j]) {
            r[j] = row[e[j]];
            c[j] = col[e[j]];
            vb[j] = __float_as_uint(fabsf(av[e[j]]));
        }
    }
    int p[4], q[4];
#pragma unroll
    for (int j = 0; j < 4; j++) {
        if (ok[j]) {
            p[j] = atomicAdd(&g_curC[c[j]], 1);
            q[j] = atomicAdd(&g_curV[r[j]], 1);
        }
    }
#pragma unroll
    for (int j = 0; j < 4; j++) {
        if (ok[j]) {
            g_cscE[p[j]] = ((u64)vb[j] << 32) | (u32)r[j];
            g_csrE[q[j]] = ((u64)vb[j] << 32) | (u32)c[j];
        }
    }
}

__global__ void init_vars_kernel(int n) {
    int i = blockIdx.x * blockDim.x + threadIdx.x;
    if (i < n) g_vars[i] = 1.0f;
}

// ===================== weight fragment packing ==============================
__global__ void conv_w_kernel(const float* __restrict__ W1, const float* __restrict__ W2,
                              u32* __restrict__ w1p, u32* __restrict__ w2p) {
    int idx = blockIdx.x * blockDim.x + threadIdx.x;   // 16384 threads
    {
        int pos  = idx & 3;
        int lane = (idx >> 2) & 31;
        int j    = (idx >> 7) & 15;
        int t    = idx >> 11;
        int k = t * 16 + 2 * (lane & 3) + ((pos & 1) ? 8 : 0);
        int n = j * 8 + (lane >> 2);
        float f0 = W1[k * 128 + n];
        float f1 = W1[(k + 1) * 128 + n];
        u32 hi, lo;
        bfsplit2(f0, f1, hi, lo);
        w1p[idx] = (pos >= 2) ? lo : hi;
    }
    if (idx < 8192) {
        int pos  = idx & 3;
        int lane = (idx >> 2) & 31;
        int j    = (idx >> 7) & 7;
        int t    = idx >> 10;
        int k = t * 16 + 2 * (lane & 3) + ((pos & 1) ? 8 : 0);
        int n = j * 8 + (lane >> 2);
        float f0 = W2[k * 64 + n];
        float f1 = W2[(k + 1) * 64 + n];
        u32 hi, lo;
        bfsplit2(f0, f1, hi, lo);
        w2p[idx] = (pos >= 2) ? lo : hi;
    }
}

__global__ void conv_w_out_kernel(const float* __restrict__ W1, const float* __restrict__ W2,
                                  u32* __restrict__ w1p, u32* __restrict__ w2p) {
    int idx = blockIdx.x * blockDim.x + threadIdx.x;   // 8192 threads
    {
        int pos  = idx & 3;
        int lane = (idx >> 2) & 31;
        int j    = (idx >> 7) & 15;
        int t    = idx >> 11;            // 0..3
        int k = t * 16 + 2 * (lane & 3) + ((pos & 1) ? 8 : 0);
        int n = j * 8 + (lane >> 2);
        float f0 = W1[k * 128 + n];
        float f1 = W1[(k + 1) * 128 + n];
        u32 hi, lo;
        bfsplit2(f0, f1, hi, lo);
        w1p[idx] = (pos >= 2) ? lo : hi;
    }
    if (idx < 2048) {
        int pos  = idx & 3;
        int lane = (idx >> 2) & 31;
        int j    = (idx >> 7) & 1;
        int t    = idx >> 8;             // 0..7
        int k = t * 16 + 2 * (lane & 3) + ((pos & 1) ? 8 : 0);
        int n = j * 8 + (lane >> 2);
        float f0 = W2[k * 16 + n];
        float f1 = W2[(k + 1) * 16 + n];
        u32 hi, lo;
        bfsplit2(f0, f1, hi, lo);
        w2p[idx] = (pos >= 2) ? lo : hi;
    }
}

// ===================== segment gather-reduce (split-lane, 2 edges/iter) =====
// Warp = 2 half-warps; half h processes edges s+h, s+h+2, ...
// Lane covers features 4q..4q+3 (q = lane&15) as float4; cross-half combine
// via shfl_xor(16); lanes 0-15 store the float4 result.
__global__ void seg_gather_kernel(const int* __restrict__ offs,
                                  const u64* __restrict__ edges,
                                  const float* __restrict__ srcF,
                                  float* __restrict__ dstF, int nseg) {
    int warp = threadIdx.x >> 5;
    int lane = threadIdx.x & 31;
    int seg  = blockIdx.x * (blockDim.x >> 5) + warp;
    if (seg >= nseg) return;

    int h = lane >> 4;          // half-warp id
    int q = lane & 15;          // feature quad id

    int s = offs[seg], e = offs[seg + 1];
    float4 acc = make_float4(0.f, 0.f, 0.f, 0.f);

    int p = s + h;              // this half's edge stream (stride 2)
    for (; p + 6 < e; p += 8) {
        u64 e0 = __ldg(&edges[p + 0]);
        u64 e1 = __ldg(&edges[p + 2]);
        u64 e2 = __ldg(&edges[p + 4]);
        u64 e3 = __ldg(&edges[p + 6]);
        float4 f0 = *(const float4*)&srcF[(size_t)(u32)e0 * FM + 4 * q];
        float4 f1 = *(const float4*)&srcF[(size_t)(u32)e1 * FM + 4 * q];
        float4 f2 = *(const float4*)&srcF[(size_t)(u32)e2 * FM + 4 * q];
        float4 f3 = *(const float4*)&srcF[(size_t)(u32)e3 * FM + 4 * q];
        float v0 = __uint_as_float((u32)(e0 >> 32));
        float v1 = __uint_as_float((u32)(e1 >> 32));
        float v2 = __uint_as_float((u32)(e2 >> 32));
        float v3 = __uint_as_float((u32)(e3 >> 32));
        acc.x += v0 * f0.x; acc.y += v0 * f0.y; acc.z += v0 * f0.z; acc.w += v0 * f0.w;
        acc.x += v1 * f1.x; acc.y += v1 * f1.y; acc.z += v1 * f1.z; acc.w += v1 * f1.w;
        acc.x += v2 * f2.x; acc.y += v2 * f2.y; acc.z += v2 * f2.z; acc.w += v2 * f2.w;
        acc.x += v3 * f3.x; acc.y += v3 * f3.y; acc.z += v3 * f3.z; acc.w += v3 * f3.w;
    }
    for (; p < e; p += 2) {
        u64 e0 = __ldg(&edges[p]);
        float4 f0 = *(const float4*)&srcF[(size_t)(u32)e0 * FM + 4 * q];
        float v0 = __uint_as_float((u32)(e0 >> 32));
        acc.x += v0 * f0.x; acc.y += v0 * f0.y; acc.z += v0 * f0.z; acc.w += v0 * f0.w;
    }

    acc.x += __shfl_xor_sync(0xFFFFFFFF, acc.x, 16);
    acc.y += __shfl_xor_sync(0xFFFFFFFF, acc.y, 16);
    acc.z += __shfl_xor_sync(0xFFFFFFFF, acc.z, 16);
    acc.w += __shfl_xor_sync(0xFFFFFFFF, acc.w, 16);

    if (lane < 16)
        *(float4*)&dstF[(size_t)seg * FM + 4 * q] = acc;
}

// ===================== MMA MLP: concat(inA,inB)->128(relu)->64 ==============
__global__ void __launch_bounds__(256) mlp_mma_kernel(
        const float* __restrict__ inA, const float* __restrict__ inB,
        float* __restrict__ outp,
        const uint4* __restrict__ w1p, const float* __restrict__ b1,
        const uint4* __restrict__ w2p, const float* __restrict__ b2,
        int rows) {
    int tid = threadIdx.x;
    int wid = tid >> 5;
    int lane = tid & 31;
    int m = lane & 3;
    int g = lane >> 2;

    int rbase = blockIdx.x * 128 + wid * 16;
    if (rbase >= rows) return;
    int r0 = rbase + g, r1 = rbase + g + 8;
    int rr0 = min(r0, rows - 1), rr1 = min(r1, rows - 1);

    float d1[16][4];
#pragma unroll
    for (int j = 0; j < 16; j++)
#pragma unroll
        for (int q = 0; q < 4; q++) d1[j][q] = 0.f;

#pragma unroll
    for (int t = 0; t < 8; t++) {
        const float* src = (t < 4) ? inA : inB;
        int kc = (t & 3) * 16 + 2 * m;
        float2 x0 = *(const float2*)&src[(size_t)rr0 * 64 + kc];
        float2 x1 = *(const float2*)&src[(size_t)rr1 * 64 + kc];
        float2 x2 = *(const float2*)&src[(size_t)rr0 * 64 + kc + 8];
        float2 x3 = *(const float2*)&src[(size_t)rr1 * 64 + kc + 8];
        u32 ah0, al0, ah1, al1, ah2, al2, ah3, al3;
        bfsplit2(x0.x, x0.y, ah0, al0);
        bfsplit2(x1.x, x1.y, ah1, al1);
        bfsplit2(x2.x, x2.y, ah2, al2);
        bfsplit2(x3.x, x3.y, ah3, al3);

        const uint4* wp = w1p + (size_t)(t * 16) * 32 + lane;
#pragma unroll
        for (int j = 0; j < 16; j++) {
            uint4 w = __ldg(&wp[j * 32]);
            mma_bf16(d1[j], ah0, ah1, ah2, ah3, w.x, w.y);
            mma_bf16(d1[j], ah0, ah1, ah2, ah3, w.z, w.w);
            mma_bf16(d1[j], al0, al1, al2, al3, w.x, w.y);
        }
    }

    float d2[8][4];
#pragma unroll
    for (int j = 0; j < 8; j++)
#pragma unroll
        for (int q = 0; q < 4; q++) d2[j][q] = 0.f;

#pragma unroll
    for (int t = 0; t < 8; t++) {
        float2 ba = *(const float2*)&b1[16 * t + 2 * m];
        float2 bb = *(const float2*)&b1[16 * t + 8 + 2 * m];
        float f0 = fmaxf(d1[2 * t][0] + ba.x, 0.f);
        float f1 = fmaxf(d1[2 * t][1] + ba.y, 0.f);
        float f2 = fmaxf(d1[2 * t][2] + ba.x, 0.f);
        float f3 = fmaxf(d1[2 * t][3] + ba.y, 0.f);
        float f4 = fmaxf(d1[2 * t + 1][0] + bb.x, 0.f);
        float f5 = fmaxf(d1[2 * t + 1][1] + bb.y, 0.f);
        float f6 = fmaxf(d1[2 * t + 1][2] + bb.x, 0.f);
        float f7 = fmaxf(d1[2 * t + 1][3] + bb.y, 0.f);
        u32 ah0, al0, ah1, al1, ah2, al2, ah3, al3;
        bfsplit2(f0, f1, ah0, al0);
        bfsplit2(f2, f3, ah1, al1);
        bfsplit2(f4, f5, ah2, al2);
        bfsplit2(f6, f7, ah3, al3);

        const uint4* wp = w2p + (size_t)(t * 8) * 32 + lane;
#pragma unroll
        for (int j = 0; j < 8; j++) {
            uint4 w = __ldg(&wp[j * 32]);
            mma_bf16(d2[j], ah0, ah1, ah2, ah3, w.x, w.y);
            mma_bf16(d2[j], ah0, ah1, ah2, ah3, w.z, w.w);
            mma_bf16(d2[j], al0, al1, al2, al3, w.x, w.y);
        }
    }

#pragma unroll
    for (int j = 0; j < 8; j++) {
        float2 b = *(const float2*)&b2[8 * j + 2 * m];
        if (r0 < rows) {
            *(float2*)&outp[(size_t)r0 * 64 + 8 * j + 2 * m] =
                make_float2(d2[j][0] + b.x, d2[j][1] + b.y);
        }
        if (r1 < rows) {
            *(float2*)&outp[(size_t)r1 * 64 + 8 * j + 2 * m] =
                make_float2(d2[j][2] + b.x, d2[j][3] + b.y);
        }
    }
}

// ===================== MMA output MLP: vars[64]->128(relu)->16 + sigmoid ====
__global__ void __launch_bounds__(256) out_mma_kernel(
        const uint4* __restrict__ w1p, const float* __restrict__ b1,
        const uint4* __restrict__ w2p, const float* __restrict__ b2,
        float* __restrict__ outp, int rows) {
    int tid = threadIdx.x;
    int wid = tid >> 5;
    int lane = tid & 31;
    int m = lane & 3;
    int g = lane >> 2;

    int rbase = blockIdx.x * 128 + wid * 16;
    if (rbase >= rows) return;
    int r0 = rbase + g, r1 = rbase + g + 8;
    int rr0 = min(r0, rows - 1), rr1 = min(r1, rows - 1);

    float d1[16][4];
#pragma unroll
    for (int j = 0; j < 16; j++)
#pragma unroll
        for (int q = 0; q < 4; q++) d1[j][q] = 0.f;

#pragma unroll
    for (int t = 0; t < 4; t++) {
        int kc = t * 16 + 2 * m;
        float2 x0 = *(const float2*)&g_vars[(size_t)rr0 * 64 + kc];
        float2 x1 = *(const float2*)&g_vars[(size_t)rr1 * 64 + kc];
        float2 x2 = *(const float2*)&g_vars[(size_t)rr0 * 64 + kc + 8];
        float2 x3 = *(const float2*)&g_vars[(size_t)rr1 * 64 + kc + 8];
        u32 ah0, al0, ah1, al1, ah2, al2, ah3, al3;
        bfsplit2(x0.x, x0.y, ah0, al0);
        bfsplit2(x1.x, x1.y, ah1, al1);
        bfsplit2(x2.x, x2.y, ah2, al2);
        bfsplit2(x3.x, x3.y, ah3, al3);

        const uint4* wp = w1p + (size_t)(t * 16) * 32 + lane;
#pragma unroll
        for (int j = 0; j < 16; j++) {
            uint4 w = __ldg(&wp[j * 32]);
            mma_bf16(d1[j], ah0, ah1, ah2, ah3, w.x, w.y);
            mma_bf16(d1[j], ah0, ah1, ah2, ah3, w.z, w.w);
            mma_bf16(d1[j], al0, al1, al2, al3, w.x, w.y);
        }
    }

    float d2[2][4];
#pragma unroll
    for (int j = 0; j < 2; j++)
#pragma unroll
        for (int q = 0; q < 4; q++) d2[j][q] = 0.f;

#pragma unroll
    for (int t = 0; t < 8; t++) {
        float2 ba = *(const float2*)&b1[16 * t + 2 * m];
        float2 bb = *(const float2*)&b1[16 * t + 8 + 2 * m];
        float f0 = fmaxf(d1[2 * t][0] + ba.x, 0.f);
        float f1 = fmaxf(d1[2 * t][1] + ba.y, 0.f);
        float f2 = fmaxf(d1[2 * t][2] + ba.x, 0.f);
        float f3 = fmaxf(d1[2 * t][3] + ba.y, 0.f);
        float f4 = fmaxf(d1[2 * t + 1][0] + bb.x, 0.f);
        float f5 = fmaxf(d1[2 * t + 1][1] + bb.y, 0.f);
        float f6 = fmaxf(d1[2 * t + 1][2] + bb.x, 0.f);
        float f7 = fmaxf(d1[2 * t + 1][3] + bb.y, 0.f);
        u32 ah0, al0, ah1, al1, ah2, al2, ah3, al3;
        bfsplit2(f0, f1, ah0, al0);
        bfsplit2(f2, f3, ah1, al1);
        bfsplit2(f4, f5, ah2, al2);
        bfsplit2(f6, f7, ah3, al3);

        const uint4* wp = w2p + (size_t)(t * 2) * 32 + lane;
#pragma unroll
        for (int j = 0; j < 2; j++) {
            uint4 w = __ldg(&wp[j * 32]);
            mma_bf16(d2[j], ah0, ah1, ah2, ah3, w.x, w.y);
            mma_bf16(d2[j], ah0, ah1, ah2, ah3, w.z, w.w);
            mma_bf16(d2[j], al0, al1, al2, al3, w.x, w.y);
        }
    }

#pragma unroll
    for (int j = 0; j < 2; j++) {
        float2 b = *(const float2*)&b2[8 * j + 2 * m];
        if (r0 < rows) {
            float z0 = d2[j][0] + b.x;
            float z1 = d2[j][1] + b.y;
            *(float2*)&outp[(size_t)r0 * OUTB + 8 * j + 2 * m] =
                make_float2(1.f / (1.f + __expf(-z0)), 1.f / (1.f + __expf(-z1)));
        }
        if (r1 < rows) {
            float z2 = d2[j][2] + b.x;
            float z3 = d2[j][3] + b.y;
            *(float2*)&outp[(size_t)r1 * OUTB + 8 * j + 2 * m] =
                make_float2(1.f / (1.f + __expf(-z2)), 1.f / (1.f + __expf(-z3)));
        }
    }
}

// ===================== scalar prep kernel ===================================
__device__ __forceinline__ void mlp_layer2_64(const float* sbuf,
                                              const float* __restrict__ W2,
                                              const float* __restrict__ b2,
                                              float* __restrict__ outp,
                                              int row0, int rows, int lane) {
    float2 acc[4];
#pragma unroll
    for (int r = 0; r < 4; r++) acc[r] = make_float2(0.f, 0.f);

    for (int k = 0; k < 128; k += 4) {
        float4 hv[4];
#pragma unroll
        for (int r = 0; r < 4; r++) hv[r] = *(const float4*)&sbuf[r * 128 + k];
#pragma unroll
        for (int kk = 0; kk < 4; kk++) {
            float2 w = *(const float2*)&W2[(k + kk) * 64 + 2 * lane];
#pragma unroll
            for (int r = 0; r < 4; r++) {
                float hk = ((const float*)&hv[r])[kk];
                acc[r].x += hk * w.x;
                acc[r].y += hk * w.y;
            }
        }
    }
    float2 bb = *(const float2*)&b2[2 * lane];
#pragma unroll
    for (int r = 0; r < 4; r++) {
        if (row0 + r < rows) {
            *(float2*)&outp[(size_t)(row0 + r) * 64 + 2 * lane] =
                make_float2(acc[r].x + bb.x, acc[r].y + bb.y);
        }
    }
}

__global__ void __launch_bounds__(256) prep_kernel(
                            const float* __restrict__ cond,
                            const float* __restrict__ w1, const float* __restrict__ b1,
                            const float* __restrict__ w2, const float* __restrict__ b2,
                            int rows) {
    __shared__ float sbuf[8][512];
    int warp = threadIdx.x >> 5;
    int lane = threadIdx.x & 31;
    int row0 = (blockIdx.x * 8 + warp) * 4;
    if (row0 >= rows) return;
    float* sbf = sbuf[warp];

    float4 w = *(const float4*)&w1[4 * lane];
    float4 b = *(const float4*)&b1[4 * lane];
#pragma unroll
    for (int r = 0; r < 4; r++) {
        int row = min(row0 + r, rows - 1);
        float c = cond[row];
        float4 h;
        h.x = fmaxf(c * w.x + b.x, 0.f);
        h.y = fmaxf(c * w.y + b.y, 0.f);
        h.z = fmaxf(c * w.z + b.z, 0.f);
        h.w = fmaxf(c * w.w + b.w, 0.f);
        *(float4*)&sbf[r * 128 + 4 * lane] = h;
    }
    __syncwarp();
    mlp_layer2_64(sbf, w2, b2, g_cons, row0, rows, lane);
}

// ===================== launch ===============================================
extern "C" void kernel_launch(void* const* d_in, const int* in_sizes, int n_in,
                              void* d_out, int out_size) {
    const int*   row  = (const int*)  d_in[0];
    const int*   col  = (const int*)  d_in[1];
    const float* adj  = (const float*)d_in[2];
    const float* cond = (const float*)d_in[3];

    int nnz = in_sizes[0];
    int C   = in_sizes[3];
    int V   = out_size / OUTB;
    if (nnz > MAXNNZ) nnz = MAXNNZ;
    if (C > MAXC) C = MAXC;
    if (V > MAXV) V = MAXV;

    int w = 4;
    if (n_in >= 22 && in_sizes[4] == 1 && in_sizes[5] == 1) w = 6;
    const float* pc_w1 = (const float*)d_in[w + 0];
    const float* pc_b1 = (const float*)d_in[w + 1];
    const float* pc_w2 = (const float*)d_in[w + 2];
    const float* pc_b2 = (const float*)d_in[w + 3];
    const float* cu_w1 = (const float*)d_in[w + 4];
    const float* cu_b1 = (const float*)d_in[w + 5];
    const float* cu_w2 = (const float*)d_in[w + 6];
    const float* cu_b2 = (const float*)d_in[w + 7];
    const float* vu_w1 = (const float*)d_in[w + 8];
    const float* vu_b1 = (const float*)d_in[w + 9];
    const float* vu_w2 = (const float*)d_in[w + 10];
    const float* vu_b2 = (const float*)d_in[w + 11];
    const float* o_w1  = (const float*)d_in[w + 12];
    const float* o_b1  = (const float*)d_in[w + 13];
    const float* o_w2  = (const float*)d_in[w + 14];
    const float* o_b2  = (const float*)d_in[w + 15];

    float *p_vars, *p_cons, *p_v2c, *p_c2v;
    int   *p_offC, *p_offV;
    u64   *p_cscE, *p_csrE;
    u32   *p_w1cu, *p_w2cu, *p_w1vu, *p_w2vu, *p_w1o, *p_w2o;
    cudaGetSymbolAddress((void**)&p_vars,  g_vars);
    cudaGetSymbolAddress((void**)&p_cons,  g_cons);
    cudaGetSymbolAddress((void**)&p_v2c,   g_v2c);
    cudaGetSymbolAddress((void**)&p_c2v,   g_c2v);
    cudaGetSymbolAddress((void**)&p_offC,  g_offC);
    cudaGetSymbolAddress((void**)&p_offV,  g_offV);
    cudaGetSymbolAddress((void**)&p_cscE,  g_cscE);
    cudaGetSymbolAddress((void**)&p_csrE,  g_csrE);
    cudaGetSymbolAddress((void**)&p_w1cu,  g_w1p_cu);
    cudaGetSymbolAddress((void**)&p_w2cu,  g_w2p_cu);
    cudaGetSymbolAddress((void**)&p_w1vu,  g_w1p_vu);
    cudaGetSymbolAddress((void**)&p_w2vu,  g_w2p_vu);
    cudaGetSymbolAddress((void**)&p_w1o,   g_w1p_out);
    cudaGetSymbolAddress((void**)&p_w2o,   g_w2p_out);

    int maxCV = (C > V) ? C : V;

    zero_counts_kernel<<<(maxCV + 255) / 256, 256>>>(C, V);
    hist_kernel<<<(nnz + 2047) / 2048, 256>>>(row, col, nnz);
    scan_kernel<<<2, 1024>>>(C, V);
    fill_kernel<<<(nnz + 1023) / 1024, 256>>>(row, col, adj, nnz);
    init_vars_kernel<<<(V * FM + 255) / 256, 256>>>(V * FM);
    conv_w_kernel<<<64, 256>>>(cu_w1, cu_w2, p_w1cu, p_w2cu);
    conv_w_kernel<<<64, 256>>>(vu_w1, vu_w2, p_w1vu, p_w2vu);
    conv_w_out_kernel<<<32, 256>>>(o_w1, o_w2, p_w1o, p_w2o);
    prep_kernel<<<(C + 31) / 32, 256>>>(cond, pc_w1, pc_b1, pc_w2, pc_b2, C);

    int gC = (C + 127) / 128;
    int gV = (V + 127) / 128;
    for (int it = 0; it < 3; it++) {
        seg_gather_kernel<<<(C + 7) / 8, 256>>>(p_offC, p_cscE, p_vars, p_v2c, C);
        mlp_mma_kernel<<<gC, 256>>>(p_cons, p_v2c, p_cons,
                                    (const uint4*)p_w1cu, cu_b1, (const uint4*)p_w2cu, cu_b2, C);
        seg_gather_kernel<<<(V + 7) / 8, 256>>>(p_offV, p_csrE, p_cons, p_c2v, V);
        mlp_mma_kernel<<<gV, 256>>>(p_vars, p_c2v, p_vars,
                                    (const uint4*)p_w1vu, vu_b1, (const uint4*)p_w2vu, vu_b2, V);
    }

    out_mma_kernel<<<gV, 256>>>((const uint4*)p_w1o, o_b1, (const uint4*)p_w2o, o_b2,
                                (float*)d_out, V);
}